// round 7
// baseline (speedup 1.0000x reference)
#include <cuda_runtime.h>
#include <cstdint>
#include <math_constants.h>

// Problem constants
#define NROWS   131072      // 256*512
#define DDIM    64
#define ECODES  1024
#define CHUNK   128         // codes per chunk
#define NCHUNK  (ECODES / CHUNK)
#define BLOCK   256
#define RPB     128         // rows per CTA
#define GRID    (NROWS / RPB)

// smem layout sizes
#define XD_STRIDE 65                    // ULL per row (64 data + 1 pad)
#define XD_ULL    (RPB * XD_STRIDE)     // 8320 ULL = 66560 B
#define W_KSTRIDE 162                   // floats per k row (16 groups * 10 + 2)
#define W_FLOATS  (DDIM * W_KSTRIDE)    // 10368 floats = 41472 B
#define SMEM_BYTES (XD_ULL*8 + W_FLOATS*4 + CHUNK*4 /*t2*/ + RPB*4 /*idx*/ + BLOCK*4 /*red*/)

typedef unsigned long long ull;

__device__ float        g_loss_acc;   // zero-init; reset to 0 by final CTA each call
__device__ unsigned int g_ctr;        // zero-init; wraps back to 0 each call

__device__ __forceinline__ ull f32x2_pack(float a, float b) {
    ull r; asm("mov.b64 %0, {%1, %2};" : "=l"(r) : "f"(a), "f"(b)); return r;
}
__device__ __forceinline__ void f32x2_unpack(ull v, float& a, float& b) {
    asm("mov.b64 {%0, %1}, %2;" : "=f"(a), "=f"(b) : "l"(v));
}
__device__ __forceinline__ ull f32x2_fma(ull a, ull b, ull c) {
    ull r; asm("fma.rn.f32x2 %0, %1, %2, %3;" : "=l"(r) : "l"(a), "l"(b), "l"(c)); return r;
}

// ---- single fused kernel: distances + argmin + all outputs + loss finalize ----
__global__ __launch_bounds__(BLOCK, 2) void vq_main_kernel(
    const float* __restrict__ inp,   // [131072, 64]
    const float* __restrict__ wt,    // [1024, 64]
    float* out_q,                    // [131072, 64] or null
    float* out_enc,                  // [131072, 1024] or null (only 4B-aligned)
    float* out_loss)                 // [1] or null
{
    extern __shared__ __align__(16) char smem_raw[];
    ull*   xdup  = reinterpret_cast<ull*>(smem_raw);                    // [128][65] (x,x) pairs
    float* wsh   = reinterpret_cast<float*>(smem_raw + XD_ULL * 8);     // [64][162] grouped codes
    float* t2sh  = wsh + W_FLOATS;                                      // [128]
    int*   idx_sh= reinterpret_cast<int*>(t2sh + CHUNK);                // [128]
    float* red   = reinterpret_cast<float*>(idx_sh + RPB);              // [256]

    const int tid = threadIdx.x;
    const int rg  = tid >> 4;        // 0..15 : row group (8 rows)
    const int cg  = tid & 15;        // 0..15 : code group (8 codes per chunk)
    const size_t rowbase = (size_t)blockIdx.x * RPB;

    // ---- stage x duplicated as (x,x) pairs; coalesced gmem read ----
    {
        const float* gx = inp + rowbase * DDIM;
        for (int i = tid; i < RPB * DDIM; i += BLOCK) {
            float v = gx[i];
            xdup[(i >> 6) * XD_STRIDE + (i & 63)] = f32x2_pack(v, v);
        }
    }
    __syncthreads();

    // ---- t1 per owned row: sequential fl(x^2) adds ----
    float t1[8];
    #pragma unroll
    for (int r = 0; r < 8; r++) {
        const float* xr = reinterpret_cast<const float*>(xdup + (rg * 8 + r) * XD_STRIDE);
        float s = 0.0f;
        #pragma unroll
        for (int k = 0; k < DDIM; k++) {
            float xv = xr[2 * k];                 // low lane of (x,x)
            s = __fadd_rn(s, __fmul_rn(xv, xv));
        }
        t1[r] = s;
    }

    float best[8]; int bidx[8];
    #pragma unroll
    for (int r = 0; r < 8; r++) { best[r] = CUDART_INF_F; bidx[r] = 0; }

    for (int ch = 0; ch < NCHUNK; ch++) {
        __syncthreads();
        // stage weight chunk: code c -> wsh[k*162 + (c>>3)*10 + (c&7)]
        {
            const float* wg = wt + (size_t)ch * CHUNK * DDIM;
            for (int i = tid; i < CHUNK * DDIM; i += BLOCK) {
                int c = i >> 6, k = i & 63;
                wsh[k * W_KSTRIDE + (c >> 3) * 10 + (c & 7)] = wg[i];
            }
            // t2 for this chunk: sequential fl(w^2) adds from gmem (L1-hot: same
            // lines as staging). Bit-identical to the former prep kernel.
            if (tid < CHUNK) {
                const float* wr = wt + (size_t)(ch * CHUNK + tid) * DDIM;
                float s = 0.0f;
                #pragma unroll
                for (int k = 0; k < DDIM; k++)
                    s = __fadd_rn(s, __fmul_rn(wr[k], wr[k]));
                t2sh[tid] = s;
            }
        }
        __syncthreads();

        ull acc[8][4];
        #pragma unroll
        for (int r = 0; r < 8; r++)
            #pragma unroll
            for (int p = 0; p < 4; p++) acc[r][p] = 0ull;

        const ull* xbase = xdup + rg * 8 * XD_STRIDE;
        #pragma unroll 2
        for (int k = 0; k < DDIM; k++) {
            ull wv[4];
            const ull* wrow = reinterpret_cast<const ull*>(wsh + k * W_KSTRIDE + cg * 10);
            #pragma unroll
            for (int p = 0; p < 4; p++) wv[p] = wrow[p];
            ull xr[8];
            #pragma unroll
            for (int r = 0; r < 8; r++) xr[r] = xbase[r * XD_STRIDE + k];
            #pragma unroll
            for (int r = 0; r < 8; r++)
                #pragma unroll
                for (int p = 0; p < 4; p++)
                    acc[r][p] = f32x2_fma(xr[r], wv[p], acc[r][p]);
        }

        // epilogue: distances + running argmin, flat loop over 8 rows.
        // Within a thread codes ascend (2p, 2p+1), strict '<' => first-index ties.
        const int cbase = ch * CHUNK + cg * 8;
        #pragma unroll
        for (int r = 0; r < 8; r++) {
            float b = best[r]; int bi = bidx[r];
            #pragma unroll
            for (int p = 0; p < 4; p++) {
                float d0, d1; f32x2_unpack(acc[r][p], d0, d1);
                float u0 = __fadd_rn(t1[r], t2sh[cg * 8 + 2 * p]);
                float dist0 = __fsub_rn(u0, __fmul_rn(2.0f, d0));
                if (dist0 < b) { b = dist0; bi = cbase + 2 * p; }
                float u1 = __fadd_rn(t1[r], t2sh[cg * 8 + 2 * p + 1]);
                float dist1 = __fsub_rn(u1, __fmul_rn(2.0f, d1));
                if (dist1 < b) { b = dist1; bi = cbase + 2 * p + 1; }
            }
            best[r] = b; bidx[r] = bi;
        }
    }

    // ---- cross-thread argmin over the 16 code-groups (width-16 shuffle) ----
    #pragma unroll
    for (int r = 0; r < 8; r++) {
        float d = best[r]; int ix = bidx[r];
        #pragma unroll
        for (int off = 1; off < 16; off <<= 1) {
            float d2 = __shfl_xor_sync(0xffffffffu, d, off, 16);
            int   i2 = __shfl_xor_sync(0xffffffffu, ix, off, 16);
            if (d2 < d || (d2 == d && i2 < ix)) { d = d2; ix = i2; }
        }
        if (cg == 0) idx_sh[rg * 8 + r] = ix;
    }

    // ---- zero encodings (alignment-safe: peel to 16B, vector body, tail) ----
    if (out_enc) {
        float* ebase = out_enc + rowbase * (size_t)ECODES;
        const int total = RPB * ECODES;
        const int head = (int)(((16u - ((uintptr_t)ebase & 15u)) & 15u) >> 2);
        if (tid < head) ebase[tid] = 0.0f;
        float4* v = reinterpret_cast<float4*>(ebase + head);
        const int nvec = (total - head) >> 2;
        float4 z = make_float4(0.f, 0.f, 0.f, 0.f);
        for (int i = tid; i < nvec; i += BLOCK) v[i] = z;
        const int tail_start = head + (nvec << 2);
        if (tid < total - tail_start) ebase[tail_start + tid] = 0.0f;
    }
    __syncthreads();   // idx_sh visible + zeros done before scatter

    if (out_enc && tid < RPB)
        out_enc[(rowbase + tid) * (size_t)ECODES + (size_t)idx_sh[tid]] = 1.0f;

    // ---- quantized_st + loss partial ----
    float part = 0.0f;
    for (int i = tid; i < RPB * DDIM; i += BLOCK) {
        int r = i >> 6, k = i & 63;
        float q  = wt[(size_t)idx_sh[r] * DDIM + k];
        float xv = inp[(rowbase + r) * DDIM + k];
        float dqx = __fsub_rn(q, xv);
        part = __fadd_rn(part, __fmul_rn(dqx, dqx));
        if (out_q)
            out_q[rowbase * DDIM + i] = __fadd_rn(xv, dqx);
    }
    red[tid] = part;
    __syncthreads();
    for (int s = BLOCK / 2; s > 0; s >>= 1) {
        if (tid < s) red[tid] += red[tid + s];
        __syncthreads();
    }

    // ---- loss accumulate + last-CTA finalize (replaces the fin kernel) ----
    if (tid == 0) {
        atomicAdd(&g_loss_acc, red[0]);
        __threadfence();
        unsigned int done = atomicAdd(&g_ctr, 1u);
        if (done == GRID - 1) {
            float m = *((volatile float*)&g_loss_acc) / 8388608.0f;
            if (out_loss) out_loss[0] = __fadd_rn(m, __fmul_rn(0.25f, m));
            g_loss_acc = 0.0f;    // restore state for next (graph-replayed) call
            __threadfence();
            g_ctr = 0u;
        }
    }
}

extern "C" void kernel_launch(void* const* d_in, const int* in_sizes, int n_in,
                              void* d_out, int out_size)
{
    const float* inp = nullptr;
    const float* wt  = nullptr;
    for (int i = 0; i < n_in; i++) {
        if (in_sizes[i] == 8388608) inp = (const float*)d_in[i];
        else if (in_sizes[i] == 65536) wt = (const float*)d_in[i];
    }
    if (!inp || !wt) return;

    float* out = (float*)d_out;
    const long long Q = 8388608LL, ENC = 134217728LL;
    long long os = (long long)out_size;

    float* oL = nullptr; float* oQ = nullptr; float* oE = nullptr;
    if (os == 1 + Q + ENC)      { oL = out; oQ = out + 1; oE = out + 1 + Q; }
    else if (os == Q + ENC)     { oQ = out; oE = out + Q; }
    else if (os == ENC)         { oE = out; }
    else if (os == Q)           { oQ = out; }
    else if (os == 1)           { oL = out; }
    else {
        oL = out;
        if (os >= 1 + Q) oQ = out + 1;
        if (os >= 1 + Q + ENC) oE = out + 1 + Q;
    }

    // opt-in to >48KB dynamic smem (idempotent; non-stream API, capture-safe)
    cudaFuncSetAttribute(vq_main_kernel,
                         cudaFuncAttributeMaxDynamicSharedMemorySize, SMEM_BYTES);

    vq_main_kernel<<<GRID, BLOCK, SMEM_BYTES>>>(inp, wt, oQ, oE, oL);
}

// round 10
// speedup vs baseline: 1.3597x; 1.3597x over previous
#include <cuda_runtime.h>
#include <cstdint>
#include <math_constants.h>

// R10 resubmission of the R8/R9 kernel (two container-level infra failures,
// zero kernel-attributable evidence; see R5->R6 precedent).

// Problem constants
#define NROWS   131072      // 256*512
#define DDIM    64
#define ECODES  1024
#define CHUNK   128         // codes per chunk
#define NCHUNK  (ECODES / CHUNK)
#define BLOCK   256
#define RPB     128         // rows per CTA
#define GRID    (NROWS / RPB)

// smem layout sizes
#define XD_STRIDE 66                    // ULL per row slot (64 data + 2 pad) = 528 B, 16B-aligned
#define XD_ULL    (RPB * XD_STRIDE)     // 8448 ULL = 67584 B
#define W_KSTRIDE 162                   // floats per k row (16 groups * 10 + 2)
#define W_FLOATS  (DDIM * W_KSTRIDE)    // 10368 floats = 41472 B
#define SMEM_BYTES (XD_ULL*8 + W_FLOATS*4 + CHUNK*4 /*t2*/ + RPB*4 /*idx*/ + BLOCK*4 /*red*/)

typedef unsigned long long ull;

__device__ float        g_loss_acc;   // zero-init; reset to 0 by final CTA each call
__device__ unsigned int g_ctr;        // zero-init; wraps back to 0 each call
__device__ float        g_t2[ECODES];

__device__ __forceinline__ ull f32x2_pack(float a, float b) {
    ull r; asm("mov.b64 %0, {%1, %2};" : "=l"(r) : "f"(a), "f"(b)); return r;
}
__device__ __forceinline__ void f32x2_unpack(ull v, float& a, float& b) {
    asm("mov.b64 {%0, %1}, %2;" : "=f"(a), "=f"(b) : "l"(v));
}
__device__ __forceinline__ ull f32x2_fma(ull a, ull b, ull c) {
    ull r; asm("fma.rn.f32x2 %0, %1, %2, %3;" : "=l"(r) : "l"(a), "l"(b), "l"(c)); return r;
}

// ---- prep: t2[c] = sum_k fl(w[c][k]^2), sequential adds ----
__global__ __launch_bounds__(256) void vq_prep_kernel(const float* __restrict__ wt) {
    int c = blockIdx.x * blockDim.x + threadIdx.x;
    if (c < ECODES) {
        const float* wr = wt + (size_t)c * DDIM;
        float s = 0.0f;
        #pragma unroll
        for (int k = 0; k < DDIM; k++)
            s = __fadd_rn(s, __fmul_rn(wr[k], wr[k]));
        g_t2[c] = s;
    }
}

// ---- main: register-blocked distances + argmin + all outputs + loss finalize ----
__global__ __launch_bounds__(BLOCK, 2) void vq_main_kernel(
    const float* __restrict__ inp,   // [131072, 64]
    const float* __restrict__ wt,    // [1024, 64]
    float* out_q,                    // [131072, 64] or null
    float* out_enc,                  // [131072, 1024] or null (only 4B-aligned)
    float* out_loss)                 // [1] or null
{
    extern __shared__ __align__(16) char smem_raw[];
    ull*   xdup  = reinterpret_cast<ull*>(smem_raw);                    // [128 slots][66] (x,x)
    float* wsh   = reinterpret_cast<float*>(smem_raw + XD_ULL * 8);     // [64][162] grouped codes
    float* t2sh  = wsh + W_FLOATS;                                      // [128]
    int*   idx_sh= reinterpret_cast<int*>(t2sh + CHUNK);                // [128]
    float* red   = reinterpret_cast<float*>(idx_sh + RPB);              // [256]

    const int tid = threadIdx.x;
    const int rg  = tid >> 4;        // 0..15 : row group (8 rows)
    const int cg  = tid & 15;        // 0..15 : code group (8 codes per chunk)
    const size_t rowbase = (size_t)blockIdx.x * RPB;

    // ---- stage x duplicated as (x,x) pairs, permuted: row -> slot = (row>>3) + (row&7)*16.
    // A warp's two row-groups (rg, rg+1) land in ADJACENT slots -> Δbank=4, conflict-free
    // broadcast for the LDS.128 reads below.
    {
        const float* gx = inp + rowbase * DDIM;
        for (int i = tid; i < RPB * DDIM; i += BLOCK) {
            int row = i >> 6, k = i & 63;
            int slot = (row >> 3) + (row & 7) * 16;
            float v = gx[i];
            xdup[slot * XD_STRIDE + k] = f32x2_pack(v, v);
        }
    }
    __syncthreads();

    // ---- t1 per owned row: sequential fl(x^2) adds (k ascending) ----
    float t1[8];
    #pragma unroll
    for (int r = 0; r < 8; r++) {
        const float* xr = reinterpret_cast<const float*>(xdup + (rg + r * 16) * XD_STRIDE);
        float s = 0.0f;
        #pragma unroll
        for (int k = 0; k < DDIM; k++) {
            float xv = xr[2 * k];                 // low lane of (x,x)
            s = __fadd_rn(s, __fmul_rn(xv, xv));
        }
        t1[r] = s;
    }

    float best[8]; int bidx[8];
    #pragma unroll
    for (int r = 0; r < 8; r++) { best[r] = CUDART_INF_F; bidx[r] = 0; }

    for (int ch = 0; ch < NCHUNK; ch++) {
        __syncthreads();
        // stage weight chunk: code c -> wsh[k*162 + (c>>3)*10 + (c&7)]
        {
            const float* wg = wt + (size_t)ch * CHUNK * DDIM;
            for (int i = tid; i < CHUNK * DDIM; i += BLOCK) {
                int c = i >> 6, k = i & 63;
                wsh[k * W_KSTRIDE + (c >> 3) * 10 + (c & 7)] = wg[i];
            }
            if (tid < CHUNK) t2sh[tid] = g_t2[ch * CHUNK + tid];
        }
        __syncthreads();

        ull acc[8][4];
        #pragma unroll
        for (int r = 0; r < 8; r++)
            #pragma unroll
            for (int p = 0; p < 4; p++) acc[r][p] = 0ull;

        // k-pair loop: one LDS.128 per row fetches (x,x) for k0 and k1.
        // Per accumulator the FMA order is k0 then k1, kp ascending -> globally
        // k-ascending sequential accumulation (bit-identical to scalar order).
        #pragma unroll 1
        for (int kp = 0; kp < DDIM / 2; kp++) {
            const int k0 = 2 * kp;
            ull w0[4], w1[4];
            const ull* w0p = reinterpret_cast<const ull*>(wsh + k0 * W_KSTRIDE + cg * 10);
            const ull* w1p = reinterpret_cast<const ull*>(wsh + (k0 + 1) * W_KSTRIDE + cg * 10);
            #pragma unroll
            for (int p = 0; p < 4; p++) { w0[p] = w0p[p]; w1[p] = w1p[p]; }

            #pragma unroll
            for (int r = 0; r < 8; r++) {
                ulonglong2 xv = *reinterpret_cast<const ulonglong2*>(
                    xdup + (rg + r * 16) * XD_STRIDE + k0);
                #pragma unroll
                for (int p = 0; p < 4; p++)
                    acc[r][p] = f32x2_fma(xv.x, w0[p], acc[r][p]);
                #pragma unroll
                for (int p = 0; p < 4; p++)
                    acc[r][p] = f32x2_fma(xv.y, w1[p], acc[r][p]);
            }
        }

        // epilogue: distances + running argmin (codes ascend, strict '<' => first-index)
        const int cbase = ch * CHUNK + cg * 8;
        #pragma unroll
        for (int r = 0; r < 8; r++) {
            float b = best[r]; int bi = bidx[r];
            #pragma unroll
            for (int p = 0; p < 4; p++) {
                float d0, d1; f32x2_unpack(acc[r][p], d0, d1);
                float u0 = __fadd_rn(t1[r], t2sh[cg * 8 + 2 * p]);
                float dist0 = __fsub_rn(u0, __fmul_rn(2.0f, d0));
                if (dist0 < b) { b = dist0; bi = cbase + 2 * p; }
                float u1 = __fadd_rn(t1[r], t2sh[cg * 8 + 2 * p + 1]);
                float dist1 = __fsub_rn(u1, __fmul_rn(2.0f, d1));
                if (dist1 < b) { b = dist1; bi = cbase + 2 * p + 1; }
            }
            best[r] = b; bidx[r] = bi;
        }
    }

    // ---- cross-thread argmin over the 16 code-groups (width-16 shuffle) ----
    #pragma unroll
    for (int r = 0; r < 8; r++) {
        float d = best[r]; int ix = bidx[r];
        #pragma unroll
        for (int off = 1; off < 16; off <<= 1) {
            float d2 = __shfl_xor_sync(0xffffffffu, d, off, 16);
            int   i2 = __shfl_xor_sync(0xffffffffu, ix, off, 16);
            if (d2 < d || (d2 == d && i2 < ix)) { d = d2; ix = i2; }
        }
        if (cg == 0) idx_sh[rg * 8 + r] = ix;
    }

    // ---- zero encodings (alignment-safe: peel to 16B, vector body, tail) ----
    if (out_enc) {
        float* ebase = out_enc + rowbase * (size_t)ECODES;
        const int total = RPB * ECODES;
        const int head = (int)(((16u - ((uintptr_t)ebase & 15u)) & 15u) >> 2);
        if (tid < head) ebase[tid] = 0.0f;
        float4* v = reinterpret_cast<float4*>(ebase + head);
        const int nvec = (total - head) >> 2;
        float4 z = make_float4(0.f, 0.f, 0.f, 0.f);
        for (int i = tid; i < nvec; i += BLOCK) v[i] = z;
        const int tail_start = head + (nvec << 2);
        if (tid < total - tail_start) ebase[tail_start + tid] = 0.0f;
    }
    __syncthreads();   // idx_sh visible + zeros done before scatter

    if (out_enc && tid < RPB)
        out_enc[(rowbase + tid) * (size_t)ECODES + (size_t)idx_sh[tid]] = 1.0f;

    // ---- quantized_st + loss partial ----
    float part = 0.0f;
    for (int i = tid; i < RPB * DDIM; i += BLOCK) {
        int r = i >> 6, k = i & 63;
        float q  = wt[(size_t)idx_sh[r] * DDIM + k];
        float xv = inp[(rowbase + r) * DDIM + k];
        float dqx = __fsub_rn(q, xv);
        part = __fadd_rn(part, __fmul_rn(dqx, dqx));
        if (out_q)
            out_q[rowbase * DDIM + i] = __fadd_rn(xv, dqx);
    }
    red[tid] = part;
    __syncthreads();
    for (int s = BLOCK / 2; s > 0; s >>= 1) {
        if (tid < s) red[tid] += red[tid + s];
        __syncthreads();
    }

    // ---- loss accumulate + last-CTA finalize ----
    if (tid == 0) {
        atomicAdd(&g_loss_acc, red[0]);
        __threadfence();
        unsigned int done = atomicAdd(&g_ctr, 1u);
        if (done == GRID - 1) {
            float m = *((volatile float*)&g_loss_acc) / 8388608.0f;
            if (out_loss) out_loss[0] = __fadd_rn(m, __fmul_rn(0.25f, m));
            g_loss_acc = 0.0f;    // restore state for next (graph-replayed) call
            __threadfence();
            g_ctr = 0u;
        }
    }
}

extern "C" void kernel_launch(void* const* d_in, const int* in_sizes, int n_in,
                              void* d_out, int out_size)
{
    const float* inp = nullptr;
    const float* wt  = nullptr;
    for (int i = 0; i < n_in; i++) {
        if (in_sizes[i] == 8388608) inp = (const float*)d_in[i];
        else if (in_sizes[i] == 65536) wt = (const float*)d_in[i];
    }
    if (!inp || !wt) return;

    float* out = (float*)d_out;
    const long long Q = 8388608LL, ENC = 134217728LL;
    long long os = (long long)out_size;

    float* oL = nullptr; float* oQ = nullptr; float* oE = nullptr;
    if (os == 1 + Q + ENC)      { oL = out; oQ = out + 1; oE = out + 1 + Q; }
    else if (os == Q + ENC)     { oQ = out; oE = out + Q; }
    else if (os == ENC)         { oE = out; }
    else if (os == Q)           { oQ = out; }
    else if (os == 1)           { oL = out; }
    else {
        oL = out;
        if (os >= 1 + Q) oQ = out + 1;
        if (os >= 1 + Q + ENC) oE = out + 1 + Q;
    }

    // opt-in to >48KB dynamic smem (idempotent; non-stream API, capture-safe)
    cudaFuncSetAttribute(vq_main_kernel,
                         cudaFuncAttributeMaxDynamicSharedMemorySize, SMEM_BYTES);

    vq_prep_kernel<<<(ECODES + 255) / 256, 256>>>(wt);
    vq_main_kernel<<<GRID, BLOCK, SMEM_BYTES>>>(inp, wt, oQ, oE, oL);
}